// round 3
// baseline (speedup 1.0000x reference)
#include <cuda_runtime.h>
#include <math.h>

#define H_    24
#define HD_   128
#define D_    3072
#define SIMG  2048
#define STXT  512
#define STOT  2560
#define ATOK  4
#define ADIM  1024

#define BQ    64
#define BKV   64
#define KPAD  132   // padded row stride (floats); 528B = 16B-aligned, conflict-free phases

// ---- scratch (allocation-free: __device__ globals) ----
__device__ float g_Q[H_*STOT*HD_];
__device__ float g_K[H_*STOT*HD_];
__device__ float g_V[H_*STOT*HD_];
__device__ float g_HS[STOT*D_];
__device__ float g_vdK[H_*ATOK*HD_];
__device__ float g_vdV[H_*ATOK*HD_];

// ============================================================
// SGEMM: C[M,N] = A[M,K] @ W[K,N] + bias
// mode 0: dst row-major [M,N]
// mode 1: scatter into head layout dst[h][s_off+row][hd], h=col>>7, hd=col&127
// Requires M%128==0, N%128==0, K%16==0.
// ============================================================
__global__ __launch_bounds__(256) void sgemm_kernel(
    const float* __restrict__ A, const float* __restrict__ W,
    const float* __restrict__ bias, float* __restrict__ dst,
    int M, int K, int N, int mode, int s_off)
{
    __shared__ float As[16][128];
    __shared__ float Bs[16][128];
    const int bm = blockIdx.y * 128, bn = blockIdx.x * 128;
    const int tid = threadIdx.x;
    const int warp = tid >> 5, lane = tid & 31;
    const int tr = (warp >> 1) * 32 + (lane >> 3) * 8;   // row within tile
    const int tc = (warp & 1) * 64 + (lane & 7) * 8;     // col within tile

    float acc[8][8];
#pragma unroll
    for (int i = 0; i < 8; i++)
#pragma unroll
        for (int j = 0; j < 8; j++) acc[i][j] = 0.f;

    for (int k0 = 0; k0 < K; k0 += 16) {
#pragma unroll
        for (int i = 0; i < 2; i++) {
            int idx = tid + i * 256;                 // 0..511
            int ar = idx >> 2, ac = (idx & 3) << 2;  // A: 128 rows x 4 float4
            float4 av = *(const float4*)(A + (size_t)(bm + ar) * K + k0 + ac);
            As[ac + 0][ar] = av.x; As[ac + 1][ar] = av.y;
            As[ac + 2][ar] = av.z; As[ac + 3][ar] = av.w;
            int br = idx >> 5, bc = (idx & 31) << 2; // B: 16 rows x 32 float4
            *(float4*)&Bs[br][bc] = *(const float4*)(W + (size_t)(k0 + br) * N + bn + bc);
        }
        __syncthreads();
#pragma unroll
        for (int k = 0; k < 16; k++) {
            float a[8], b[8];
            *(float4*)&a[0] = *(float4*)&As[k][tr];
            *(float4*)&a[4] = *(float4*)&As[k][tr + 4];
            *(float4*)&b[0] = *(float4*)&Bs[k][tc];
            *(float4*)&b[4] = *(float4*)&Bs[k][tc + 4];
#pragma unroll
            for (int i = 0; i < 8; i++)
#pragma unroll
                for (int j = 0; j < 8; j++)
                    acc[i][j] = fmaf(a[i], b[j], acc[i][j]);
        }
        __syncthreads();
    }

#pragma unroll
    for (int i = 0; i < 8; i++) {
        int row = bm + tr + i;
#pragma unroll
        for (int j = 0; j < 8; j++) {
            int col = bn + tc + j;
            float c = acc[i][j] + (bias ? bias[col] : 0.f);
            if (mode == 0) {
                dst[(size_t)row * N + col] = c;
            } else {
                int h = col >> 7, hd = col & 127;
                dst[((size_t)h * STOT + (s_off + row)) * HD_ + hd] = c;
            }
        }
    }
}

// ============================================================
// Adapter K/V projection: [4,1024] @ [1024,3072] -> head layout
// ============================================================
__global__ __launch_bounds__(256) void adapter_proj_kernel(
    const float* __restrict__ A, const float* __restrict__ Wk,
    const float* __restrict__ Wv)
{
    int j = blockIdx.x * 256 + threadIdx.x;   // 0..3071
    int m = blockIdx.y;                       // 0..3
    float ak = 0.f, av = 0.f;
    for (int k = 0; k < ADIM; k++) {
        float a = A[m * ADIM + k];
        ak = fmaf(a, Wk[(size_t)k * D_ + j], ak);
        av = fmaf(a, Wv[(size_t)k * D_ + j], av);
    }
    int h = j >> 7, hd = j & 127;
    g_vdK[(h * ATOK + m) * HD_ + hd] = ak;
    g_vdV[(h * ATOK + m) * HD_ + hd] = av;
}

// ============================================================
// Per-head RMSNorm + RoPE (in place on [H][STOT][HD] buffer)
// Rows s < STXT use w_add (text), s >= STXT use w_main (image).
// ============================================================
__global__ __launch_bounds__(128) void rms_rope_kernel(
    float* __restrict__ buf, const float* __restrict__ w_main,
    const float* __restrict__ w_add, const float* __restrict__ fc,
    const float* __restrict__ fs)
{
    int s = blockIdx.x, h = blockIdx.y, t = threadIdx.x;
    float* p = buf + ((size_t)h * STOT + s) * HD_;
    float x = p[t];
    float v = x * x;
#pragma unroll
    for (int o = 16; o > 0; o >>= 1) v += __shfl_xor_sync(0xffffffffu, v, o);
    __shared__ float ws[4];
    __shared__ float ys[HD_];
    if ((t & 31) == 0) ws[t >> 5] = v;
    __syncthreads();
    float sum = ws[0] + ws[1] + ws[2] + ws[3];
    const float* w = (s < STXT) ? w_add : w_main;
    float y = x * rsqrtf(sum * (1.f / HD_) + 1e-6f) * w[t];
    ys[t] = y;
    __syncthreads();
    float rot = (t & 1) ? ys[t - 1] : -ys[t + 1];
    p[t] = y * fc[s * HD_ + t] + rot * fs[s * HD_ + t];
}

// ============================================================
// Flash attention (fp32 online softmax) + fused 4-token adapter
// cross attention. Grid: (STOT/BQ, H). 256 threads, warp owns
// 8 query rows. Lane l owns keys l and l+32 of each KV tile.
// Q pre-scaled by 1/sqrt(HD) so the adapter branch reuses it.
// ============================================================
__global__ __launch_bounds__(256) void flash_kernel(const float* __restrict__ bscale)
{
    extern __shared__ float smf[];
    float* Qs = smf;                    // BQ*HD
    float* Ks = Qs + BQ * HD_;          // BKV*KPAD
    float* Vs = Ks + BKV * KPAD;        // BKV*KPAD
    float* Ps = Vs + BKV * KPAD;        // BQ*BKV
    float* aK = Ps + BQ * BKV;          // ATOK*HD
    float* aV = aK + ATOK * HD_;        // ATOK*HD

    const int h = blockIdx.y;
    const int q0 = blockIdx.x * BQ;
    const int tid = threadIdx.x, warp = tid >> 5, lane = tid & 31;
    const float scale = 0.08838834764831845f;   // 1/sqrt(128)

    const float* Qg = g_Q + (size_t)h * STOT * HD_;
    const float* Kg = g_K + (size_t)h * STOT * HD_;
    const float* Vg = g_V + (size_t)h * STOT * HD_;

    // stage Q tile (pre-scaled)
#pragma unroll
    for (int i = 0; i < 8; i++) {
        int idx = tid + i * 256;    // 2048 float4 = 64*128 floats
        float4 v = *(const float4*)(Qg + (size_t)q0 * HD_ + idx * 4);
        v.x *= scale; v.y *= scale; v.z *= scale; v.w *= scale;
        *(float4*)(Qs + idx * 4) = v;
    }
    // stage adapter K/V (512 floats each)
    if (tid < 128) {
        *(float4*)(aK + tid * 4) = *(const float4*)(g_vdK + (size_t)h * ATOK * HD_ + tid * 4);
        *(float4*)(aV + tid * 4) = *(const float4*)(g_vdV + (size_t)h * ATOK * HD_ + tid * 4);
    }

    float acc[8][4];
    float mrow[8], lrow[8];
#pragma unroll
    for (int r = 0; r < 8; r++) {
        mrow[r] = -1e30f; lrow[r] = 0.f;
#pragma unroll
        for (int c = 0; c < 4; c++) acc[r][c] = 0.f;
    }
    const int row0 = warp * 8;

    for (int t = 0; t < STOT / BKV; t++) {
        int k0 = t * BKV;
        __syncthreads();   // prior tile fully consumed; also fences Qs/aK/aV on t==0
#pragma unroll
        for (int i = 0; i < 8; i++) {
            int idx = tid + i * 256;                 // key = idx>>5, hd4 = (idx&31)*4
            int key = idx >> 5, hd4 = (idx & 31) << 2;
            *(float4*)(Ks + key * KPAD + hd4) =
                *(const float4*)(Kg + (size_t)(k0 + key) * HD_ + hd4);
            *(float4*)(Vs + key * KPAD + hd4) =
                *(const float4*)(Vg + (size_t)(k0 + key) * HD_ + hd4);
        }
        __syncthreads();

        // ---- scores: lane owns keys lane and lane+32 ----
        float s[8][2];
#pragma unroll
        for (int r = 0; r < 8; r++) { s[r][0] = 0.f; s[r][1] = 0.f; }
        const float* kr0 = Ks + lane * KPAD;
        const float* kr1 = kr0 + 32 * KPAD;
#pragma unroll 8
        for (int hh = 0; hh < HD_; hh += 4) {
            float4 k0v = *(const float4*)(kr0 + hh);
            float4 k1v = *(const float4*)(kr1 + hh);
#pragma unroll
            for (int r = 0; r < 8; r++) {
                float4 q = *(const float4*)(Qs + (row0 + r) * HD_ + hh);
                s[r][0] += q.x * k0v.x + q.y * k0v.y + q.z * k0v.z + q.w * k0v.w;
                s[r][1] += q.x * k1v.x + q.y * k1v.y + q.z * k1v.z + q.w * k1v.w;
            }
        }

        // ---- online softmax per row ----
#pragma unroll
        for (int r = 0; r < 8; r++) {
            float sm2 = fmaxf(s[r][0], s[r][1]);
#pragma unroll
            for (int o = 16; o > 0; o >>= 1)
                sm2 = fmaxf(sm2, __shfl_xor_sync(0xffffffffu, sm2, o));
            float mnew = fmaxf(mrow[r], sm2);
            float corr = __expf(mrow[r] - mnew);
            float p0 = __expf(s[r][0] - mnew);
            float p1 = __expf(s[r][1] - mnew);
            float ps = p0 + p1;
#pragma unroll
            for (int o = 16; o > 0; o >>= 1)
                ps += __shfl_xor_sync(0xffffffffu, ps, o);
            lrow[r] = lrow[r] * corr + ps;
            mrow[r] = mnew;
#pragma unroll
            for (int c = 0; c < 4; c++) acc[r][c] *= corr;
            Ps[(row0 + r) * BKV + lane] = p0;
            Ps[(row0 + r) * BKV + 32 + lane] = p1;
        }
        __syncwarp();

        // ---- PV: acc[r][c] += sum_k P[r][k] * V[k][lane+32c] ----
#pragma unroll 4
        for (int kk = 0; kk < BKV; kk += 4) {
            float vv[4][4];
#pragma unroll
            for (int i = 0; i < 4; i++)
#pragma unroll
                for (int c = 0; c < 4; c++)
                    vv[i][c] = Vs[(kk + i) * KPAD + lane + 32 * c];
#pragma unroll
            for (int r = 0; r < 8; r++) {
                float4 p = *(const float4*)(Ps + (row0 + r) * BKV + kk);
#pragma unroll
                for (int c = 0; c < 4; c++)
                    acc[r][c] += p.x * vv[0][c] + p.y * vv[1][c]
                               + p.z * vv[2][c] + p.w * vv[3][c];
            }
        }
        __syncwarp();
    }

    // ---- epilogue: normalize + fused adapter cross-attention ----
    float sb = bscale[0];   // SCALE(=1.0) * block_scaler
#pragma unroll
    for (int r = 0; r < 8; r++) {
        int row = row0 + r;
        float inv = 1.f / lrow[r];
        float at[ATOK];
#pragma unroll
        for (int tt = 0; tt < ATOK; tt++) {
            float part = 0.f;
#pragma unroll
            for (int c = 0; c < 4; c++)
                part += Qs[row * HD_ + lane + 32 * c] * aK[tt * HD_ + lane + 32 * c];
#pragma unroll
            for (int o = 16; o > 0; o >>= 1)
                part += __shfl_xor_sync(0xffffffffu, part, o);
            at[tt] = part;   // already includes 1/sqrt(HD) via scaled Qs
        }
        float am = fmaxf(fmaxf(at[0], at[1]), fmaxf(at[2], at[3]));
        float e0 = __expf(at[0] - am), e1 = __expf(at[1] - am);
        float e2 = __expf(at[2] - am), e3 = __expf(at[3] - am);
        float einv = 1.f / (e0 + e1 + e2 + e3);
#pragma unroll
        for (int c = 0; c < 4; c++) {
            int hd = lane + 32 * c;
            float vd = (e0 * aV[0 * HD_ + hd] + e1 * aV[1 * HD_ + hd]
                      + e2 * aV[2 * HD_ + hd] + e3 * aV[3 * HD_ + hd]) * einv;
            float o = acc[r][c] * inv + sb * vd;
            g_HS[(size_t)(q0 + row) * D_ + h * HD_ + hd] = o;
        }
    }
}

// ============================================================
// launch
// ============================================================
extern "C" void kernel_launch(void* const* d_in, const int* in_sizes, int n_in,
                              void* d_out, int out_size)
{
    (void)in_sizes; (void)n_in; (void)out_size;
    const float* hidden   = (const float*)d_in[0];
    const float* enc      = (const float*)d_in[1];
    const float* adapter  = (const float*)d_in[2];
    const float* fcos     = (const float*)d_in[3];
    const float* fsin     = (const float*)d_in[4];
    const float* Wq       = (const float*)d_in[5];
    const float* bq       = (const float*)d_in[6];
    const float* Wk       = (const float*)d_in[7];
    const float* bk       = (const float*)d_in[8];
    const float* Wv       = (const float*)d_in[9];
    const float* bv       = (const float*)d_in[10];
    const float* norm_q_w = (const float*)d_in[11];
    const float* norm_k_w = (const float*)d_in[12];
    const float* Wq_add   = (const float*)d_in[13];
    const float* bq_add   = (const float*)d_in[14];
    const float* Wk_add   = (const float*)d_in[15];
    const float* bk_add   = (const float*)d_in[16];
    const float* Wv_add   = (const float*)d_in[17];
    const float* bv_add   = (const float*)d_in[18];
    const float* nq_add_w = (const float*)d_in[19];
    const float* nk_add_w = (const float*)d_in[20];
    const float* Wo       = (const float*)d_in[21];
    const float* bo       = (const float*)d_in[22];
    const float* Wo_add   = (const float*)d_in[23];
    const float* bo_add   = (const float*)d_in[24];
    const float* Wk_adapt = (const float*)d_in[25];
    const float* Wv_adapt = (const float*)d_in[26];
    const float* bscaler  = (const float*)d_in[27];
    float* out = (float*)d_out;

    float *Qp, *Kp, *Vp, *HSp;
    cudaGetSymbolAddress((void**)&Qp, g_Q);
    cudaGetSymbolAddress((void**)&Kp, g_K);
    cudaGetSymbolAddress((void**)&Vp, g_V);
    cudaGetSymbolAddress((void**)&HSp, g_HS);

    dim3 gImg(D_ / 128, SIMG / 128);   // 24 x 16
    dim3 gTxt(D_ / 128, STXT / 128);   // 24 x 4

    // image-token QKV projections (scatter into head layout at s_off=STXT)
    sgemm_kernel<<<gImg, 256>>>(hidden, Wq, bq, Qp, SIMG, D_, D_, 1, STXT);
    sgemm_kernel<<<gImg, 256>>>(hidden, Wk, bk, Kp, SIMG, D_, D_, 1, STXT);
    sgemm_kernel<<<gImg, 256>>>(hidden, Wv, bv, Vp, SIMG, D_, D_, 1, STXT);
    // text-token QKV projections (s_off=0)
    sgemm_kernel<<<gTxt, 256>>>(enc, Wq_add, bq_add, Qp, STXT, D_, D_, 1, 0);
    sgemm_kernel<<<gTxt, 256>>>(enc, Wk_add, bk_add, Kp, STXT, D_, D_, 1, 0);
    sgemm_kernel<<<gTxt, 256>>>(enc, Wv_add, bv_add, Vp, STXT, D_, D_, 1, 0);
    // adapter K/V
    adapter_proj_kernel<<<dim3(D_ / 256, ATOK), 256>>>(adapter, Wk_adapt, Wv_adapt);
    // per-head RMSNorm + RoPE on Q and K
    rms_rope_kernel<<<dim3(STOT, H_), 128>>>(Qp, norm_q_w, nq_add_w, fcos, fsin);
    rms_rope_kernel<<<dim3(STOT, H_), 128>>>(Kp, norm_k_w, nk_add_w, fcos, fsin);
    // flash attention + fused adapter branch
    int smem_bytes = (BQ * HD_ + 2 * BKV * KPAD + BQ * BKV + 2 * ATOK * HD_) * 4;
    cudaFuncSetAttribute(flash_kernel, cudaFuncAttributeMaxDynamicSharedMemorySize,
                         smem_bytes);
    flash_kernel<<<dim3(STOT / BQ, H_), 256, smem_bytes>>>(bscaler);
    // output projections: img_out first, then enc_out (reference tuple order)
    sgemm_kernel<<<gImg, 256>>>(HSp + (size_t)STXT * D_, Wo, bo, out,
                                SIMG, D_, D_, 0, 0);
    sgemm_kernel<<<gTxt, 256>>>(HSp, Wo_add, bo_add, out + (size_t)SIMG * D_,
                                STXT, D_, D_, 0, 0);
}

// round 9
// speedup vs baseline: 1.5723x; 1.5723x over previous
#include <cuda_runtime.h>
#include <cuda_bf16.h>
#include <stdint.h>
#include <math.h>

#define H_    24
#define HD_   128
#define D_    3072
#define SIMG  2048
#define STXT  512
#define STOT  2560
#define ATOK  4
#define ADIM  1024

#define BQ    64
#define BKV   64
#define KPAD  132   // flash: padded row stride (floats); 528B, 16B-aligned

#define ASTR  36    // mma gemm smem A row stride (floats), 144B: 16B-aligned
#define BSTR  132   // mma gemm smem B row stride (floats), 528B: 16B-aligned

// ---- scratch (allocation-free: __device__ globals) ----
__device__ float g_Q[H_*STOT*HD_];
__device__ float g_K[H_*STOT*HD_];
__device__ float g_V[H_*STOT*HD_];
__device__ float g_HS[STOT*D_];
__device__ float g_vdK[H_*ATOK*HD_];
__device__ float g_vdV[H_*ATOK*HD_];

// ============================================================
// bf16 split-3 tensor-core GEMM: C[M,N] = A[M,K] @ W[K,N] + bias
// fp32 in/out; operands split hi/lo bf16 in registers; 3 MMAs
// (hi*hi + hi*lo + lo*hi) give ~2^-16 relative accuracy.
// mode 0: dst row-major [M,N]
// mode 1: scatter into head layout dst[h][s_off+row][hd]
// Requires M%128==0, N%128==0, K%32==0.
// ============================================================
__device__ __forceinline__ void mma_bf16(float* acc,
    uint32_t a0, uint32_t a1, uint32_t a2, uint32_t a3,
    uint32_t b0, uint32_t b1)
{
    asm volatile(
        "mma.sync.aligned.m16n8k16.row.col.f32.bf16.bf16.f32 "
        "{%0,%1,%2,%3}, {%4,%5,%6,%7}, {%8,%9}, {%0,%1,%2,%3};\n"
        : "+f"(acc[0]), "+f"(acc[1]), "+f"(acc[2]), "+f"(acc[3])
        : "r"(a0), "r"(a1), "r"(a2), "r"(a3), "r"(b0), "r"(b1));
}

__device__ __forceinline__ void pack_hilo(float x, float y,
                                          uint32_t& hi, uint32_t& lo)
{
    __nv_bfloat162 h = __floats2bfloat162_rn(x, y);
    float2 hf = __bfloat1622float2(h);
    __nv_bfloat162 l = __floats2bfloat162_rn(x - hf.x, y - hf.y);
    hi = *reinterpret_cast<uint32_t*>(&h);
    lo = *reinterpret_cast<uint32_t*>(&l);
}

__device__ __forceinline__ void cp16(uint32_t smem_dst, const float* gsrc)
{
    asm volatile("cp.async.cg.shared.global [%0], [%1], 16;\n"
                 :: "r"(smem_dst), "l"(gsrc));
}

__global__ __launch_bounds__(256) void mma_gemm_kernel(
    const float* __restrict__ A, const float* __restrict__ W,
    const float* __restrict__ bias, float* __restrict__ dst,
    int M, int K, int N, int mode, int s_off)
{
    extern __shared__ float sm[];
    float* As0 = sm;
    float* As1 = As0 + 128 * ASTR;
    float* Bs0 = As1 + 128 * ASTR;
    float* Bs1 = Bs0 + 32 * BSTR;
    float* Asb[2] = { As0, As1 };
    float* Bsb[2] = { Bs0, Bs1 };

    const int bm = blockIdx.y * 128, bn = blockIdx.x * 128;
    const int tid = threadIdx.x;
    const int warp = tid >> 5, lane = tid & 31;
    const int wm = warp >> 2, wn = warp & 3;      // warp grid 2x4
    const int g = lane >> 2, tig = lane & 3;

    float acc[4][4][4];
#pragma unroll
    for (int mi = 0; mi < 4; mi++)
#pragma unroll
        for (int ni = 0; ni < 4; ni++)
#pragma unroll
            for (int e = 0; e < 4; e++) acc[mi][ni][e] = 0.f;

    const int nChunks = K / 32;

    // ---- stage chunk c into buffer b (cp.async, 16B) ----
    auto stage = [&](int c, int b) {
#pragma unroll
        for (int i = 0; i < 4; i++) {
            int idx = tid + i * 256;                  // 0..1023
            int row = idx >> 3, c4 = (idx & 7) << 2;  // A: 128 rows x 8 f4
            cp16((uint32_t)__cvta_generic_to_shared(&Asb[b][row * ASTR + c4]),
                 A + (size_t)(bm + row) * K + c * 32 + c4);
            int br = idx >> 5, n4 = (idx & 31) << 2;  // B: 32 rows x 32 f4
            cp16((uint32_t)__cvta_generic_to_shared(&Bsb[b][br * BSTR + n4]),
                 W + (size_t)(c * 32 + br) * N + bn + n4);
        }
    };

    stage(0, 0);
    asm volatile("cp.async.commit_group;\n" ::: "memory");

    for (int c = 0; c < nChunks; c++) {
        if (c + 1 < nChunks) {
            stage(c + 1, (c + 1) & 1);
            asm volatile("cp.async.commit_group;\n" ::: "memory");
            asm volatile("cp.async.wait_group 1;\n" ::: "memory");
        } else {
            asm volatile("cp.async.wait_group 0;\n" ::: "memory");
        }
        __syncthreads();

        const float* Asx = Asb[c & 1];
        const float* Bsx = Bsb[c & 1];
#pragma unroll
        for (int s = 0; s < 2; s++) {
            const int kb = s * 16;
            // B fragments (col = wn*32 + ni*8 + g, k rows kb+2tig..)
            uint32_t bh[4][2], bl[4][2];
#pragma unroll
            for (int ni = 0; ni < 4; ni++) {
                int n = wn * 32 + ni * 8 + g;
                float x0 = Bsx[(kb + 2 * tig) * BSTR + n];
                float x1 = Bsx[(kb + 2 * tig + 1) * BSTR + n];
                float x2 = Bsx[(kb + 2 * tig + 8) * BSTR + n];
                float x3 = Bsx[(kb + 2 * tig + 9) * BSTR + n];
                pack_hilo(x0, x1, bh[ni][0], bl[ni][0]);
                pack_hilo(x2, x3, bh[ni][1], bl[ni][1]);
            }
#pragma unroll
            for (int mi = 0; mi < 4; mi++) {
                int R = wm * 64 + mi * 16;
                float2 f0 = *(const float2*)&Asx[(R + g) * ASTR + kb + 2 * tig];
                float2 f1 = *(const float2*)&Asx[(R + g + 8) * ASTR + kb + 2 * tig];
                float2 f2 = *(const float2*)&Asx[(R + g) * ASTR + kb + 2 * tig + 8];
                float2 f3 = *(const float2*)&Asx[(R + g + 8) * ASTR + kb + 2 * tig + 8];
                uint32_t ah[4], al[4];
                pack_hilo(f0.x, f0.y, ah[0], al[0]);
                pack_hilo(f1.x, f1.y, ah[1], al[1]);
                pack_hilo(f2.x, f2.y, ah[2], al[2]);
                pack_hilo(f3.x, f3.y, ah[3], al[3]);
#pragma unroll
                for (int ni = 0; ni < 4; ni++) {
                    mma_bf16(acc[mi][ni], ah[0], ah[1], ah[2], ah[3],
                             bh[ni][0], bh[ni][1]);
                    mma_bf16(acc[mi][ni], ah[0], ah[1], ah[2], ah[3],
                             bl[ni][0], bl[ni][1]);
                    mma_bf16(acc[mi][ni], al[0], al[1], al[2], al[3],
                             bh[ni][0], bh[ni][1]);
                }
            }
        }
        __syncthreads();
    }

    // ---- epilogue ----
#pragma unroll
    for (int mi = 0; mi < 4; mi++) {
        int r0 = bm + wm * 64 + mi * 16 + g;
#pragma unroll
        for (int ni = 0; ni < 4; ni++) {
            int cb = bn + wn * 32 + ni * 8 + 2 * tig;
            float b0 = bias ? bias[cb] : 0.f;
            float b1 = bias ? bias[cb + 1] : 0.f;
            float2 v0 = make_float2(acc[mi][ni][0] + b0, acc[mi][ni][1] + b1);
            float2 v1 = make_float2(acc[mi][ni][2] + b0, acc[mi][ni][3] + b1);
            if (mode == 0) {
                *(float2*)&dst[(size_t)r0 * N + cb] = v0;
                *(float2*)&dst[(size_t)(r0 + 8) * N + cb] = v1;
            } else {
                int h = cb >> 7, hd = cb & 127;
                *(float2*)&dst[((size_t)h * STOT + (s_off + r0)) * HD_ + hd] = v0;
                *(float2*)&dst[((size_t)h * STOT + (s_off + r0 + 8)) * HD_ + hd] = v1;
            }
        }
    }
}

// ============================================================
// Adapter K/V projection: [4,1024] @ [1024,3072] -> head layout
// ============================================================
__global__ __launch_bounds__(256) void adapter_proj_kernel(
    const float* __restrict__ A, const float* __restrict__ Wk,
    const float* __restrict__ Wv)
{
    int j = blockIdx.x * 256 + threadIdx.x;   // 0..3071
    int m = blockIdx.y;                       // 0..3
    float ak = 0.f, av = 0.f;
    for (int k = 0; k < ADIM; k++) {
        float a = A[m * ADIM + k];
        ak = fmaf(a, Wk[(size_t)k * D_ + j], ak);
        av = fmaf(a, Wv[(size_t)k * D_ + j], av);
    }
    int h = j >> 7, hd = j & 127;
    g_vdK[(h * ATOK + m) * HD_ + hd] = ak;
    g_vdV[(h * ATOK + m) * HD_ + hd] = av;
}

// ============================================================
// Per-head RMSNorm + RoPE (in place on [H][STOT][HD] buffer)
// ============================================================
__global__ __launch_bounds__(128) void rms_rope_kernel(
    float* __restrict__ buf, const float* __restrict__ w_main,
    const float* __restrict__ w_add, const float* __restrict__ fc,
    const float* __restrict__ fs)
{
    int s = blockIdx.x, h = blockIdx.y, t = threadIdx.x;
    float* p = buf + ((size_t)h * STOT + s) * HD_;
    float x = p[t];
    float v = x * x;
#pragma unroll
    for (int o = 16; o > 0; o >>= 1) v += __shfl_xor_sync(0xffffffffu, v, o);
    __shared__ float ws[4];
    __shared__ float ys[HD_];
    if ((t & 31) == 0) ws[t >> 5] = v;
    __syncthreads();
    float sum = ws[0] + ws[1] + ws[2] + ws[3];
    const float* w = (s < STXT) ? w_add : w_main;
    float y = x * rsqrtf(sum * (1.f / HD_) + 1e-6f) * w[t];
    ys[t] = y;
    __syncthreads();
    float rot = (t & 1) ? ys[t - 1] : -ys[t + 1];
    p[t] = y * fc[s * HD_ + t] + rot * fs[s * HD_ + t];
}

// ============================================================
// Flash attention (fp32 online softmax) + fused 4-token adapter
// cross attention. Grid: (STOT/BQ, H). 256 threads.
// ============================================================
__global__ __launch_bounds__(256) void flash_kernel(const float* __restrict__ bscale)
{
    extern __shared__ float smf[];
    float* Qs = smf;                    // BQ*HD
    float* Ks = Qs + BQ * HD_;          // BKV*KPAD
    float* Vs = Ks + BKV * KPAD;        // BKV*KPAD
    float* Ps = Vs + BKV * KPAD;        // BQ*BKV
    float* aK = Ps + BQ * BKV;          // ATOK*HD
    float* aV = aK + ATOK * HD_;        // ATOK*HD

    const int h = blockIdx.y;
    const int q0 = blockIdx.x * BQ;
    const int tid = threadIdx.x, warp = tid >> 5, lane = tid & 31;
    const float scale = 0.08838834764831845f;   // 1/sqrt(128)

    const float* Qg = g_Q + (size_t)h * STOT * HD_;
    const float* Kg = g_K + (size_t)h * STOT * HD_;
    const float* Vg = g_V + (size_t)h * STOT * HD_;

#pragma unroll
    for (int i = 0; i < 8; i++) {
        int idx = tid + i * 256;
        float4 v = *(const float4*)(Qg + (size_t)q0 * HD_ + idx * 4);
        v.x *= scale; v.y *= scale; v.z *= scale; v.w *= scale;
        *(float4*)(Qs + idx * 4) = v;
    }
    if (tid < 128) {
        *(float4*)(aK + tid * 4) = *(const float4*)(g_vdK + (size_t)h * ATOK * HD_ + tid * 4);
        *(float4*)(aV + tid * 4) = *(const float4*)(g_vdV + (size_t)h * ATOK * HD_ + tid * 4);
    }

    float acc[8][4];
    float mrow[8], lrow[8];
#pragma unroll
    for (int r = 0; r < 8; r++) {
        mrow[r] = -1e30f; lrow[r] = 0.f;
#pragma unroll
        for (int c = 0; c < 4; c++) acc[r][c] = 0.f;
    }
    const int row0 = warp * 8;

    for (int t = 0; t < STOT / BKV; t++) {
        int k0 = t * BKV;
        __syncthreads();
#pragma unroll
        for (int i = 0; i < 8; i++) {
            int idx = tid + i * 256;
            int key = idx >> 5, hd4 = (idx & 31) << 2;
            *(float4*)(Ks + key * KPAD + hd4) =
                *(const float4*)(Kg + (size_t)(k0 + key) * HD_ + hd4);
            *(float4*)(Vs + key * KPAD + hd4) =
                *(const float4*)(Vg + (size_t)(k0 + key) * HD_ + hd4);
        }
        __syncthreads();

        float s[8][2];
#pragma unroll
        for (int r = 0; r < 8; r++) { s[r][0] = 0.f; s[r][1] = 0.f; }
        const float* kr0 = Ks + lane * KPAD;
        const float* kr1 = kr0 + 32 * KPAD;
#pragma unroll 8
        for (int hh = 0; hh < HD_; hh += 4) {
            float4 k0v = *(const float4*)(kr0 + hh);
            float4 k1v = *(const float4*)(kr1 + hh);
#pragma unroll
            for (int r = 0; r < 8; r++) {
                float4 q = *(const float4*)(Qs + (row0 + r) * HD_ + hh);
                s[r][0] += q.x * k0v.x + q.y * k0v.y + q.z * k0v.z + q.w * k0v.w;
                s[r][1] += q.x * k1v.x + q.y * k1v.y + q.z * k1v.z + q.w * k1v.w;
            }
        }

#pragma unroll
        for (int r = 0; r < 8; r++) {
            float sm2 = fmaxf(s[r][0], s[r][1]);
#pragma unroll
            for (int o = 16; o > 0; o >>= 1)
                sm2 = fmaxf(sm2, __shfl_xor_sync(0xffffffffu, sm2, o));
            float mnew = fmaxf(mrow[r], sm2);
            float corr = __expf(mrow[r] - mnew);
            float p0 = __expf(s[r][0] - mnew);
            float p1 = __expf(s[r][1] - mnew);
            float ps = p0 + p1;
#pragma unroll
            for (int o = 16; o > 0; o >>= 1)
                ps += __shfl_xor_sync(0xffffffffu, ps, o);
            lrow[r] = lrow[r] * corr + ps;
            mrow[r] = mnew;
#pragma unroll
            for (int c = 0; c < 4; c++) acc[r][c] *= corr;
            Ps[(row0 + r) * BKV + lane] = p0;
            Ps[(row0 + r) * BKV + 32 + lane] = p1;
        }
        __syncwarp();

#pragma unroll 4
        for (int kk = 0; kk < BKV; kk += 4) {
            float vv[4][4];
#pragma unroll
            for (int i = 0; i < 4; i++)
#pragma unroll
                for (int c = 0; c < 4; c++)
                    vv[i][c] = Vs[(kk + i) * KPAD + lane + 32 * c];
#pragma unroll
            for (int r = 0; r < 8; r++) {
                float4 p = *(const float4*)(Ps + (row0 + r) * BKV + kk);
#pragma unroll
                for (int c = 0; c < 4; c++)
                    acc[r][c] += p.x * vv[0][c] + p.y * vv[1][c]
                               + p.z * vv[2][c] + p.w * vv[3][c];
            }
        }
        __syncwarp();
    }

    float sb = bscale[0];
#pragma unroll
    for (int r = 0; r < 8; r++) {
        int row = row0 + r;
        float inv = 1.f / lrow[r];
        float at[ATOK];
#pragma unroll
        for (int tt = 0; tt < ATOK; tt++) {
            float part = 0.f;
#pragma unroll
            for (int c = 0; c < 4; c++)
                part += Qs[row * HD_ + lane + 32 * c] * aK[tt * HD_ + lane + 32 * c];
#pragma unroll
            for (int o = 16; o > 0; o >>= 1)
                part += __shfl_xor_sync(0xffffffffu, part, o);
            at[tt] = part;
        }
        float am = fmaxf(fmaxf(at[0], at[1]), fmaxf(at[2], at[3]));
        float e0 = __expf(at[0] - am), e1 = __expf(at[1] - am);
        float e2 = __expf(at[2] - am), e3 = __expf(at[3] - am);
        float einv = 1.f / (e0 + e1 + e2 + e3);
#pragma unroll
        for (int c = 0; c < 4; c++) {
            int hd = lane + 32 * c;
            float vd = (e0 * aV[0 * HD_ + hd] + e1 * aV[1 * HD_ + hd]
                      + e2 * aV[2 * HD_ + hd] + e3 * aV[3 * HD_ + hd]) * einv;
            float o = acc[r][c] * inv + sb * vd;
            g_HS[(size_t)(q0 + row) * D_ + h * HD_ + hd] = o;
        }
    }
}

// ============================================================
// launch
// ============================================================
extern "C" void kernel_launch(void* const* d_in, const int* in_sizes, int n_in,
                              void* d_out, int out_size)
{
    (void)in_sizes; (void)n_in; (void)out_size;
    const float* hidden   = (const float*)d_in[0];
    const float* enc      = (const float*)d_in[1];
    const float* adapter  = (const float*)d_in[2];
    const float* fcos     = (const float*)d_in[3];
    const float* fsin     = (const float*)d_in[4];
    const float* Wq       = (const float*)d_in[5];
    const float* bq       = (const float*)d_in[6];
    const float* Wk       = (const float*)d_in[7];
    const float* bk       = (const float*)d_in[8];
    const float* Wv       = (const float*)d_in[9];
    const float* bv       = (const float*)d_in[10];
    const float* norm_q_w = (const float*)d_in[11];
    const float* norm_k_w = (const float*)d_in[12];
    const float* Wq_add   = (const float*)d_in[13];
    const float* bq_add   = (const float*)d_in[14];
    const float* Wk_add   = (const float*)d_in[15];
    const float* bk_add   = (const float*)d_in[16];
    const float* Wv_add   = (const float*)d_in[17];
    const float* bv_add   = (const float*)d_in[18];
    const float* nq_add_w = (const float*)d_in[19];
    const float* nk_add_w = (const float*)d_in[20];
    const float* Wo       = (const float*)d_in[21];
    const float* bo       = (const float*)d_in[22];
    const float* Wo_add   = (const float*)d_in[23];
    const float* bo_add   = (const float*)d_in[24];
    const float* Wk_adapt = (const float*)d_in[25];
    const float* Wv_adapt = (const float*)d_in[26];
    const float* bscaler  = (const float*)d_in[27];
    float* out = (float*)d_out;

    float *Qp, *Kp, *Vp, *HSp;
    cudaGetSymbolAddress((void**)&Qp, g_Q);
    cudaGetSymbolAddress((void**)&Kp, g_K);
    cudaGetSymbolAddress((void**)&Vp, g_V);
    cudaGetSymbolAddress((void**)&HSp, g_HS);

    int gemm_smem = (2 * 128 * ASTR + 2 * 32 * BSTR) * 4;   // 70656 B
    cudaFuncSetAttribute(mma_gemm_kernel,
                         cudaFuncAttributeMaxDynamicSharedMemorySize, gemm_smem);

    dim3 gImg(D_ / 128, SIMG / 128);   // 24 x 16
    dim3 gTxt(D_ / 128, STXT / 128);   // 24 x 4

    // image-token QKV projections (scatter into head layout at s_off=STXT)
    mma_gemm_kernel<<<gImg, 256, gemm_smem>>>(hidden, Wq, bq, Qp, SIMG, D_, D_, 1, STXT);
    mma_gemm_kernel<<<gImg, 256, gemm_smem>>>(hidden, Wk, bk, Kp, SIMG, D_, D_, 1, STXT);
    mma_gemm_kernel<<<gImg, 256, gemm_smem>>>(hidden, Wv, bv, Vp, SIMG, D_, D_, 1, STXT);
    // text-token QKV projections (s_off=0)
    mma_gemm_kernel<<<gTxt, 256, gemm_smem>>>(enc, Wq_add, bq_add, Qp, STXT, D_, D_, 1, 0);
    mma_gemm_kernel<<<gTxt, 256, gemm_smem>>>(enc, Wk_add, bk_add, Kp, STXT, D_, D_, 1, 0);
    mma_gemm_kernel<<<gTxt, 256, gemm_smem>>>(enc, Wv_add, bv_add, Vp, STXT, D_, D_, 1, 0);
    // adapter K/V
    adapter_proj_kernel<<<dim3(D_ / 256, ATOK), 256>>>(adapter, Wk_adapt, Wv_adapt);
    // per-head RMSNorm + RoPE on Q and K
    rms_rope_kernel<<<dim3(STOT, H_), 128>>>(Qp, norm_q_w, nq_add_w, fcos, fsin);
    rms_rope_kernel<<<dim3(STOT, H_), 128>>>(Kp, norm_k_w, nk_add_w, fcos, fsin);
    // flash attention + fused adapter branch
    int smem_bytes = (BQ * HD_ + 2 * BKV * KPAD + BQ * BKV + 2 * ATOK * HD_) * 4;
    cudaFuncSetAttribute(flash_kernel, cudaFuncAttributeMaxDynamicSharedMemorySize,
                         smem_bytes);
    flash_kernel<<<dim3(STOT / BQ, H_), 256, smem_bytes>>>(bscaler);
    // output projections: img_out first, then enc_out (reference tuple order)
    mma_gemm_kernel<<<gImg, 256, gemm_smem>>>(HSp + (size_t)STXT * D_, Wo, bo, out,
                                              SIMG, D_, D_, 0, 0);
    mma_gemm_kernel<<<gTxt, 256, gemm_smem>>>(HSp, Wo_add, bo_add, out + (size_t)SIMG * D_,
                                              STXT, D_, D_, 0, 0);
}

// round 10
// speedup vs baseline: 1.6620x; 1.0570x over previous
#include <cuda_runtime.h>
#include <cuda_bf16.h>
#include <stdint.h>
#include <math.h>

#define H_    24
#define HD_   128
#define D_    3072
#define SIMG  2048
#define STXT  512
#define STOT  2560
#define ATOK  4
#define ADIM  1024

#define BQ    64
#define BKV   64
#define KPAD  132   // flash: padded row stride (floats); 528B, 16B-aligned

#define TSTR  36    // gemm smem tile row stride in bf16 elements (72B)
#define TSEG  (128*TSTR)   // one tile segment, bf16 elements

// ---- scratch (allocation-free: __device__ globals) ----
__device__ float g_Q[H_*STOT*HD_];
__device__ float g_K[H_*STOT*HD_];
__device__ float g_V[H_*STOT*HD_];
__device__ float g_HS[STOT*D_];
__device__ float g_vdK[H_*ATOK*HD_];
__device__ float g_vdV[H_*ATOK*HD_];

// ============================================================
// bf16 split-3 tensor-core GEMM: C[M,N] = A[M,K] @ W[K,N] + bias
// fp32 in/out. hi/lo bf16 split done ONCE per element at smem
// store time; mainloop is pure LDS.32 + HMMA (3 MMAs:
// hi*hi + hi*lo + lo*hi, ~2^-16 relative accuracy).
// smem tiles (bf16, stride TSTR): A_hi/A_lo [row][k] 128x32,
// B_hi/B_lo [n][k] 128x32 (transposed at staging).
// mode 0: dst row-major [M,N]
// mode 1: scatter into head layout dst[h][s_off+row][hd]
// Requires M%128==0, N%128==0, K%32==0.
// ============================================================
__device__ __forceinline__ void mma_bf16(float* acc,
    uint32_t a0, uint32_t a1, uint32_t a2, uint32_t a3,
    uint32_t b0, uint32_t b1)
{
    asm volatile(
        "mma.sync.aligned.m16n8k16.row.col.f32.bf16.bf16.f32 "
        "{%0,%1,%2,%3}, {%4,%5,%6,%7}, {%8,%9}, {%0,%1,%2,%3};\n"
        : "+f"(acc[0]), "+f"(acc[1]), "+f"(acc[2]), "+f"(acc[3])
        : "r"(a0), "r"(a1), "r"(a2), "r"(a3), "r"(b0), "r"(b1));
}

__device__ __forceinline__ void pack_hilo(float x, float y,
                                          uint32_t& hi, uint32_t& lo)
{
    __nv_bfloat162 h = __floats2bfloat162_rn(x, y);
    float2 hf = __bfloat1622float2(h);
    __nv_bfloat162 l = __floats2bfloat162_rn(x - hf.x, y - hf.y);
    hi = *reinterpret_cast<uint32_t*>(&h);
    lo = *reinterpret_cast<uint32_t*>(&l);
}

__global__ __launch_bounds__(256) void mma_gemm_kernel(
    const float* __restrict__ A, const float* __restrict__ W,
    const float* __restrict__ bias, float* __restrict__ dst,
    int M, int K, int N, int mode, int s_off)
{
    extern __shared__ char smraw[];
    // word-level (uint32 = bf16x2) views of the 8 tile segments:
    // [Ah0 Ah1 Al0 Al1 Bh0 Bh1 Bl0 Bl1], each TSEG bf16 = TSEG/2 words
    uint32_t* base = (uint32_t*)smraw;
    const int SEGW = TSEG / 2;                 // words per segment (2304)

    const int bm = blockIdx.y * 128, bn = blockIdx.x * 128;
    const int tid = threadIdx.x;
    const int warp = tid >> 5, lane = tid & 31;
    const int wm = warp >> 2, wn = warp & 3;      // warp grid 2x4
    const int g = lane >> 2, tig = lane & 3;

    float acc[4][4][4];
#pragma unroll
    for (int mi = 0; mi < 4; mi++)
#pragma unroll
        for (int ni = 0; ni < 4; ni++)
#pragma unroll
            for (int e = 0; e < 4; e++) acc[mi][ni][e] = 0.f;

    const int nChunks = K / 32;

    float4 rA[4];
    float  rB[16];

    // ---- load chunk c globals into registers ----
    auto loadRegs = [&](int c) {
#pragma unroll
        for (int i = 0; i < 4; i++) {
            int j = tid + i * 256;                // 0..1023
            int row = j >> 3, kc = (j & 7) << 2;  // A: 128 rows x 8 f4
            rA[i] = *(const float4*)(A + (size_t)(bm + row) * K + c * 32 + kc);
        }
#pragma unroll
        for (int i = 0; i < 4; i++) {
            int q = tid + i * 256;
            int n = q & 127, kc = (q >> 7) << 2;  // B: per (n, 4 k-vals)
#pragma unroll
            for (int u = 0; u < 4; u++)
                rB[i * 4 + u] = W[(size_t)(c * 32 + kc + u) * N + bn + n];
        }
    };

    // ---- convert regs -> bf16 hi/lo smem tiles (buffer b) ----
    auto convertStore = [&](int b) {
        uint32_t* AhW = base + b * SEGW;
        uint32_t* AlW = base + (2 + b) * SEGW;
        uint32_t* BhW = base + (4 + b) * SEGW;
        uint32_t* BlW = base + (6 + b) * SEGW;
#pragma unroll
        for (int i = 0; i < 4; i++) {
            int j = tid + i * 256;
            int row = j >> 3, kc = (j & 7) << 2;
            uint32_t h0, l0, h1, l1;
            pack_hilo(rA[i].x, rA[i].y, h0, l0);
            pack_hilo(rA[i].z, rA[i].w, h1, l1);
            int w = row * (TSTR / 2) + (kc >> 1);
            AhW[w] = h0; AhW[w + 1] = h1;
            AlW[w] = l0; AlW[w + 1] = l1;
        }
#pragma unroll
        for (int i = 0; i < 4; i++) {
            int q = tid + i * 256;
            int n = q & 127, kc = (q >> 7) << 2;
            uint32_t h0, l0, h1, l1;
            pack_hilo(rB[i * 4 + 0], rB[i * 4 + 1], h0, l0);
            pack_hilo(rB[i * 4 + 2], rB[i * 4 + 3], h1, l1);
            int w = n * (TSTR / 2) + (kc >> 1);
            BhW[w] = h0; BhW[w + 1] = h1;
            BlW[w] = l0; BlW[w + 1] = l1;
        }
    };

    loadRegs(0);
    convertStore(0);
    __syncthreads();

    for (int c = 0; c < nChunks; c++) {
        if (c + 1 < nChunks) loadRegs(c + 1);

        const int b = c & 1;
        const uint32_t* AhW = base + b * SEGW;
        const uint32_t* AlW = base + (2 + b) * SEGW;
        const uint32_t* BhW = base + (4 + b) * SEGW;
        const uint32_t* BlW = base + (6 + b) * SEGW;

#pragma unroll
        for (int s = 0; s < 2; s++) {
            const int kb2 = s * 8;   // k-offset in words (s*16 elements / 2)
            uint32_t bh[4][2], bl[4][2];
#pragma unroll
            for (int ni = 0; ni < 4; ni++) {
                int n = wn * 32 + ni * 8 + g;
                int w = n * (TSTR / 2) + kb2 + tig;
                bh[ni][0] = BhW[w]; bh[ni][1] = BhW[w + 4];
                bl[ni][0] = BlW[w]; bl[ni][1] = BlW[w + 4];
            }
#pragma unroll
            for (int mi = 0; mi < 4; mi++) {
                int R = wm * 64 + mi * 16;
                int w0 = (R + g) * (TSTR / 2) + kb2 + tig;
                int w1 = (R + g + 8) * (TSTR / 2) + kb2 + tig;
                uint32_t ah[4], al[4];
                ah[0] = AhW[w0]; ah[1] = AhW[w1];
                ah[2] = AhW[w0 + 4]; ah[3] = AhW[w1 + 4];
                al[0] = AlW[w0]; al[1] = AlW[w1];
                al[2] = AlW[w0 + 4]; al[3] = AlW[w1 + 4];
#pragma unroll
                for (int ni = 0; ni < 4; ni++) {
                    mma_bf16(acc[mi][ni], ah[0], ah[1], ah[2], ah[3],
                             bh[ni][0], bh[ni][1]);
                    mma_bf16(acc[mi][ni], ah[0], ah[1], ah[2], ah[3],
                             bl[ni][0], bl[ni][1]);
                    mma_bf16(acc[mi][ni], al[0], al[1], al[2], al[3],
                             bh[ni][0], bh[ni][1]);
                }
            }
        }

        if (c + 1 < nChunks) convertStore((c + 1) & 1);
        __syncthreads();
    }

    // ---- epilogue ----
#pragma unroll
    for (int mi = 0; mi < 4; mi++) {
        int r0 = bm + wm * 64 + mi * 16 + g;
#pragma unroll
        for (int ni = 0; ni < 4; ni++) {
            int cb = bn + wn * 32 + ni * 8 + 2 * tig;
            float b0 = bias ? bias[cb] : 0.f;
            float b1 = bias ? bias[cb + 1] : 0.f;
            float2 v0 = make_float2(acc[mi][ni][0] + b0, acc[mi][ni][1] + b1);
            float2 v1 = make_float2(acc[mi][ni][2] + b0, acc[mi][ni][3] + b1);
            if (mode == 0) {
                *(float2*)&dst[(size_t)r0 * N + cb] = v0;
                *(float2*)&dst[(size_t)(r0 + 8) * N + cb] = v1;
            } else {
                int h = cb >> 7, hd = cb & 127;
                *(float2*)&dst[((size_t)h * STOT + (s_off + r0)) * HD_ + hd] = v0;
                *(float2*)&dst[((size_t)h * STOT + (s_off + r0 + 8)) * HD_ + hd] = v1;
            }
        }
    }
}

// ============================================================
// Adapter K/V projection: [4,1024] @ [1024,3072] -> head layout
// ============================================================
__global__ __launch_bounds__(256) void adapter_proj_kernel(
    const float* __restrict__ A, const float* __restrict__ Wk,
    const float* __restrict__ Wv)
{
    int j = blockIdx.x * 256 + threadIdx.x;   // 0..3071
    int m = blockIdx.y;                       // 0..3
    float ak = 0.f, av = 0.f;
    for (int k = 0; k < ADIM; k++) {
        float a = A[m * ADIM + k];
        ak = fmaf(a, Wk[(size_t)k * D_ + j], ak);
        av = fmaf(a, Wv[(size_t)k * D_ + j], av);
    }
    int h = j >> 7, hd = j & 127;
    g_vdK[(h * ATOK + m) * HD_ + hd] = ak;
    g_vdV[(h * ATOK + m) * HD_ + hd] = av;
}

// ============================================================
// Per-head RMSNorm + RoPE (in place on [H][STOT][HD] buffer)
// ============================================================
__global__ __launch_bounds__(128) void rms_rope_kernel(
    float* __restrict__ buf, const float* __restrict__ w_main,
    const float* __restrict__ w_add, const float* __restrict__ fc,
    const float* __restrict__ fs)
{
    int s = blockIdx.x, h = blockIdx.y, t = threadIdx.x;
    float* p = buf + ((size_t)h * STOT + s) * HD_;
    float x = p[t];
    float v = x * x;
#pragma unroll
    for (int o = 16; o > 0; o >>= 1) v += __shfl_xor_sync(0xffffffffu, v, o);
    __shared__ float ws[4];
    __shared__ float ys[HD_];
    if ((t & 31) == 0) ws[t >> 5] = v;
    __syncthreads();
    float sum = ws[0] + ws[1] + ws[2] + ws[3];
    const float* w = (s < STXT) ? w_add : w_main;
    float y = x * rsqrtf(sum * (1.f / HD_) + 1e-6f) * w[t];
    ys[t] = y;
    __syncthreads();
    float rot = (t & 1) ? ys[t - 1] : -ys[t + 1];
    p[t] = y * fc[s * HD_ + t] + rot * fs[s * HD_ + t];
}

// ============================================================
// Flash attention (fp32 online softmax) + fused 4-token adapter
// cross attention. Grid: (STOT/BQ, H). 256 threads.
// ============================================================
__global__ __launch_bounds__(256) void flash_kernel(const float* __restrict__ bscale)
{
    extern __shared__ float smf[];
    float* Qs = smf;                    // BQ*HD
    float* Ks = Qs + BQ * HD_;          // BKV*KPAD
    float* Vs = Ks + BKV * KPAD;        // BKV*KPAD
    float* Ps = Vs + BKV * KPAD;        // BQ*BKV
    float* aK = Ps + BQ * BKV;          // ATOK*HD
    float* aV = aK + ATOK * HD_;        // ATOK*HD

    const int h = blockIdx.y;
    const int q0 = blockIdx.x * BQ;
    const int tid = threadIdx.x, warp = tid >> 5, lane = tid & 31;
    const float scale = 0.08838834764831845f;   // 1/sqrt(128)

    const float* Qg = g_Q + (size_t)h * STOT * HD_;
    const float* Kg = g_K + (size_t)h * STOT * HD_;
    const float* Vg = g_V + (size_t)h * STOT * HD_;

#pragma unroll
    for (int i = 0; i < 8; i++) {
        int idx = tid + i * 256;
        float4 v = *(const float4*)(Qg + (size_t)q0 * HD_ + idx * 4);
        v.x *= scale; v.y *= scale; v.z *= scale; v.w *= scale;
        *(float4*)(Qs + idx * 4) = v;
    }
    if (tid < 128) {
        *(float4*)(aK + tid * 4) = *(const float4*)(g_vdK + (size_t)h * ATOK * HD_ + tid * 4);
        *(float4*)(aV + tid * 4) = *(const float4*)(g_vdV + (size_t)h * ATOK * HD_ + tid * 4);
    }

    float acc[8][4];
    float mrow[8], lrow[8];
#pragma unroll
    for (int r = 0; r < 8; r++) {
        mrow[r] = -1e30f; lrow[r] = 0.f;
#pragma unroll
        for (int c = 0; c < 4; c++) acc[r][c] = 0.f;
    }
    const int row0 = warp * 8;

    for (int t = 0; t < STOT / BKV; t++) {
        int k0 = t * BKV;
        __syncthreads();
#pragma unroll
        for (int i = 0; i < 8; i++) {
            int idx = tid + i * 256;
            int key = idx >> 5, hd4 = (idx & 31) << 2;
            *(float4*)(Ks + key * KPAD + hd4) =
                *(const float4*)(Kg + (size_t)(k0 + key) * HD_ + hd4);
            *(float4*)(Vs + key * KPAD + hd4) =
                *(const float4*)(Vg + (size_t)(k0 + key) * HD_ + hd4);
        }
        __syncthreads();

        float s[8][2];
#pragma unroll
        for (int r = 0; r < 8; r++) { s[r][0] = 0.f; s[r][1] = 0.f; }
        const float* kr0 = Ks + lane * KPAD;
        const float* kr1 = kr0 + 32 * KPAD;
#pragma unroll 8
        for (int hh = 0; hh < HD_; hh += 4) {
            float4 k0v = *(const float4*)(kr0 + hh);
            float4 k1v = *(const float4*)(kr1 + hh);
#pragma unroll
            for (int r = 0; r < 8; r++) {
                float4 q = *(const float4*)(Qs + (row0 + r) * HD_ + hh);
                s[r][0] += q.x * k0v.x + q.y * k0v.y + q.z * k0v.z + q.w * k0v.w;
                s[r][1] += q.x * k1v.x + q.y * k1v.y + q.z * k1v.z + q.w * k1v.w;
            }
        }

#pragma unroll
        for (int r = 0; r < 8; r++) {
            float sm2 = fmaxf(s[r][0], s[r][1]);
#pragma unroll
            for (int o = 16; o > 0; o >>= 1)
                sm2 = fmaxf(sm2, __shfl_xor_sync(0xffffffffu, sm2, o));
            float mnew = fmaxf(mrow[r], sm2);
            float corr = __expf(mrow[r] - mnew);
            float p0 = __expf(s[r][0] - mnew);
            float p1 = __expf(s[r][1] - mnew);
            float ps = p0 + p1;
#pragma unroll
            for (int o = 16; o > 0; o >>= 1)
                ps += __shfl_xor_sync(0xffffffffu, ps, o);
            lrow[r] = lrow[r] * corr + ps;
            mrow[r] = mnew;
#pragma unroll
            for (int c = 0; c < 4; c++) acc[r][c] *= corr;
            Ps[(row0 + r) * BKV + lane] = p0;
            Ps[(row0 + r) * BKV + 32 + lane] = p1;
        }
        __syncwarp();

#pragma unroll 4
        for (int kk = 0; kk < BKV; kk += 4) {
            float vv[4][4];
#pragma unroll
            for (int i = 0; i < 4; i++)
#pragma unroll
                for (int c = 0; c < 4; c++)
                    vv[i][c] = Vs[(kk + i) * KPAD + lane + 32 * c];
#pragma unroll
            for (int r = 0; r < 8; r++) {
                float4 p = *(const float4*)(Ps + (row0 + r) * BKV + kk);
#pragma unroll
                for (int c = 0; c < 4; c++)
                    acc[r][c] += p.x * vv[0][c] + p.y * vv[1][c]
                               + p.z * vv[2][c] + p.w * vv[3][c];
            }
        }
        __syncwarp();
    }

    float sb = bscale[0];
#pragma unroll
    for (int r = 0; r < 8; r++) {
        int row = row0 + r;
        float inv = 1.f / lrow[r];
        float at[ATOK];
#pragma unroll
        for (int tt = 0; tt < ATOK; tt++) {
            float part = 0.f;
#pragma unroll
            for (int c = 0; c < 4; c++)
                part += Qs[row * HD_ + lane + 32 * c] * aK[tt * HD_ + lane + 32 * c];
#pragma unroll
            for (int o = 16; o > 0; o >>= 1)
                part += __shfl_xor_sync(0xffffffffu, part, o);
            at[tt] = part;
        }
        float am = fmaxf(fmaxf(at[0], at[1]), fmaxf(at[2], at[3]));
        float e0 = __expf(at[0] - am), e1 = __expf(at[1] - am);
        float e2 = __expf(at[2] - am), e3 = __expf(at[3] - am);
        float einv = 1.f / (e0 + e1 + e2 + e3);
#pragma unroll
        for (int c = 0; c < 4; c++) {
            int hd = lane + 32 * c;
            float vd = (e0 * aV[0 * HD_ + hd] + e1 * aV[1 * HD_ + hd]
                      + e2 * aV[2 * HD_ + hd] + e3 * aV[3 * HD_ + hd]) * einv;
            float o = acc[r][c] * inv + sb * vd;
            g_HS[(size_t)(q0 + row) * D_ + h * HD_ + hd] = o;
        }
    }
}

// ============================================================
// launch
// ============================================================
extern "C" void kernel_launch(void* const* d_in, const int* in_sizes, int n_in,
                              void* d_out, int out_size)
{
    (void)in_sizes; (void)n_in; (void)out_size;
    const float* hidden   = (const float*)d_in[0];
    const float* enc      = (const float*)d_in[1];
    const float* adapter  = (const float*)d_in[2];
    const float* fcos     = (const float*)d_in[3];
    const float* fsin     = (const float*)d_in[4];
    const float* Wq       = (const float*)d_in[5];
    const float* bq       = (const float*)d_in[6];
    const float* Wk       = (const float*)d_in[7];
    const float* bk       = (const float*)d_in[8];
    const float* Wv       = (const float*)d_in[9];
    const float* bv       = (const float*)d_in[10];
    const float* norm_q_w = (const float*)d_in[11];
    const float* norm_k_w = (const float*)d_in[12];
    const float* Wq_add   = (const float*)d_in[13];
    const float* bq_add   = (const float*)d_in[14];
    const float* Wk_add   = (const float*)d_in[15];
    const float* bk_add   = (const float*)d_in[16];
    const float* Wv_add   = (const float*)d_in[17];
    const float* bv_add   = (const float*)d_in[18];
    const float* nq_add_w = (const float*)d_in[19];
    const float* nk_add_w = (const float*)d_in[20];
    const float* Wo       = (const float*)d_in[21];
    const float* bo       = (const float*)d_in[22];
    const float* Wo_add   = (const float*)d_in[23];
    const float* bo_add   = (const float*)d_in[24];
    const float* Wk_adapt = (const float*)d_in[25];
    const float* Wv_adapt = (const float*)d_in[26];
    const float* bscaler  = (const float*)d_in[27];
    float* out = (float*)d_out;

    float *Qp, *Kp, *Vp, *HSp;
    cudaGetSymbolAddress((void**)&Qp, g_Q);
    cudaGetSymbolAddress((void**)&Kp, g_K);
    cudaGetSymbolAddress((void**)&Vp, g_V);
    cudaGetSymbolAddress((void**)&HSp, g_HS);

    int gemm_smem = 8 * TSEG * 2;   // 8 bf16 tile segments = 73728 B
    cudaFuncSetAttribute(mma_gemm_kernel,
                         cudaFuncAttributeMaxDynamicSharedMemorySize, gemm_smem);

    dim3 gImg(D_ / 128, SIMG / 128);   // 24 x 16
    dim3 gTxt(D_ / 128, STXT / 128);   // 24 x 4

    // image-token QKV projections (scatter into head layout at s_off=STXT)
    mma_gemm_kernel<<<gImg, 256, gemm_smem>>>(hidden, Wq, bq, Qp, SIMG, D_, D_, 1, STXT);
    mma_gemm_kernel<<<gImg, 256, gemm_smem>>>(hidden, Wk, bk, Kp, SIMG, D_, D_, 1, STXT);
    mma_gemm_kernel<<<gImg, 256, gemm_smem>>>(hidden, Wv, bv, Vp, SIMG, D_, D_, 1, STXT);
    // text-token QKV projections (s_off=0)
    mma_gemm_kernel<<<gTxt, 256, gemm_smem>>>(enc, Wq_add, bq_add, Qp, STXT, D_, D_, 1, 0);
    mma_gemm_kernel<<<gTxt, 256, gemm_smem>>>(enc, Wk_add, bk_add, Kp, STXT, D_, D_, 1, 0);
    mma_gemm_kernel<<<gTxt, 256, gemm_smem>>>(enc, Wv_add, bv_add, Vp, STXT, D_, D_, 1, 0);
    // adapter K/V
    adapter_proj_kernel<<<dim3(D_ / 256, ATOK), 256>>>(adapter, Wk_adapt, Wv_adapt);
    // per-head RMSNorm + RoPE on Q and K
    rms_rope_kernel<<<dim3(STOT, H_), 128>>>(Qp, norm_q_w, nq_add_w, fcos, fsin);
    rms_rope_kernel<<<dim3(STOT, H_), 128>>>(Kp, norm_k_w, nk_add_w, fcos, fsin);
    // flash attention + fused adapter branch
    int smem_bytes = (BQ * HD_ + 2 * BKV * KPAD + BQ * BKV + 2 * ATOK * HD_) * 4;
    cudaFuncSetAttribute(flash_kernel, cudaFuncAttributeMaxDynamicSharedMemorySize,
                         smem_bytes);
    flash_kernel<<<dim3(STOT / BQ, H_), 256, smem_bytes>>>(bscaler);
    // output projections: img_out first, then enc_out (reference tuple order)
    mma_gemm_kernel<<<gImg, 256, gemm_smem>>>(HSp + (size_t)STXT * D_, Wo, bo, out,
                                              SIMG, D_, D_, 0, 0);
    mma_gemm_kernel<<<gTxt, 256, gemm_smem>>>(HSp, Wo_add, bo_add, out + (size_t)SIMG * D_,
                                              STXT, D_, D_, 0, 0);
}